// round 8
// baseline (speedup 1.0000x reference)
#include <cuda_runtime.h>
#include <cuda_pipeline.h>
#include <cuda_fp16.h>
#include <mma.h>
#include <math.h>

using namespace nvcuda;

#define NN 20000
#define EE 320000
#define TE (EE + NN)   // edges + self loops

// ---------------- device scratch (no allocations allowed) ----------------
__device__ __half g_xh[NN * 256];     // x in fp16 (GEMM1 A)
__device__ __half g_W1h[256 * 512];   // W1 in fp16
__device__ __half g_W2h[512 * 256];   // W2 in fp16
__device__ __half g_h1h[NN * 512];    // layer1 linear output, fp16 (gather-only)
__device__ __half g_out1h[NN * 512];  // layer1 aggregated+bias+gelu, fp16 (GEMM2 A)
__device__ __half g_h2h[NN * 256];    // layer2 linear output, fp16 (gather-only)
__device__ float  g_asrc1[NN * 4];
__device__ float  g_adst1[NN * 4];
__device__ float  g_asrc2[NN];
__device__ float  g_adst2[NN];
__device__ float  g_den1[NN * 4];
__device__ float  g_den2[NN];
__device__ float  g_alpha1[TE * 4];   // unnormalized exp weights, CSR order
__device__ float  g_alpha2[TE];
__device__ int    g_rowptr[NN + 1];
__device__ int    g_col[TE];          // src node per CSR slot
__device__ int    g_deg[NN];          // edge-only indegree (self loop added in scan)
__device__ int    g_cursor[NN];
__device__ int    g_src[EE];
__device__ int    g_dst[EE];
__device__ int    g_is64;

// -------- detect edge dtype (thread 0) + zero degree array (whole grid) ----
__global__ void k_detect_zero(const void* ei) {
    int i = blockIdx.x * 256 + threadIdx.x;
    if (i < NN) g_deg[i] = 0;
    if (i == 0) {
        const unsigned long long* p = (const unsigned long long*)ei;
        int ok64 = 1;
        for (int k = 0; k < 4; k++) if (p[k] >= (unsigned long long)NN) ok64 = 0;
        g_is64 = ok64;
    }
}

// ---------------- fp32 -> fp16 conversions (x, W1, W2 in one launch) ------
#define XH_N (NN * 256)
#define W1_N (256 * 512)
#define W2_N (512 * 256)
__global__ void k_f2h(const float* __restrict__ x, const float* __restrict__ W1,
                      const float* __restrict__ W2)
{
    int i = blockIdx.x * 256 + threadIdx.x;    // one float4 per thread
    int tot4 = (XH_N + W1_N + W2_N) / 4;
    if (i >= tot4) return;
    const float* src;
    __half* dst;
    int off;
    if (i < XH_N / 4)                 { src = x;  dst = g_xh;  off = i; }
    else if (i < (XH_N + W1_N) / 4)   { src = W1; dst = g_W1h; off = i - XH_N / 4; }
    else                              { src = W2; dst = g_W2h; off = i - (XH_N + W1_N) / 4; }
    float4 v = *(const float4*)&src[off * 4];
    union { uint2 u; __half2 h[2]; } pk;
    pk.h[0] = __floats2half2_rn(v.x, v.y);
    pk.h[1] = __floats2half2_rn(v.z, v.w);
    *(uint2*)&dst[off * 4] = pk.u;
}

// ---------------- edge convert + histogram ----------------
__global__ void k_convert_hist(const void* ei, int E) {
    int i = blockIdx.x * 256 + threadIdx.x;
    if (i >= E) return;
    int s, d;
    if (g_is64) {
        const long long* p = (const long long*)ei;
        s = (int)p[i]; d = (int)p[E + i];
    } else {
        const int* p = (const int*)ei;
        s = p[i]; d = p[E + i];
    }
    s = min(max(s, 0), NN - 1);
    d = min(max(d, 0), NN - 1);
    g_src[i] = s; g_dst[i] = d;
    atomicAdd(&g_deg[d], 1);
}

// ------------- exclusive scan: smem-staged, 1024 thr x 20 elems ------------
#define SCAN_PT 20                    // 1024*20 = 20480 >= NN
#define SCAN_SMEM (20480 * 4)         // 80 KB dynamic
__global__ void k_scan() {
    extern __shared__ int sdeg[];     // 20480 ints
    int t = threadIdx.x;
    // coalesced load: 5120 int4 slots, 1024 threads x 5
    #pragma unroll
    for (int i = 0; i < 5; i++) {
        int idx = i * 1024 + t;       // int4 index
        if (idx < NN / 4) {
            *(int4*)&sdeg[idx * 4] = *(const int4*)&g_deg[idx * 4];
        } else {
            *(int4*)&sdeg[idx * 4] = make_int4(0, 0, 0, 0);
        }
    }
    __syncthreads();

    int base = t * SCAN_PT;
    int v[SCAN_PT];
    int sum = 0;
    #pragma unroll
    for (int k = 0; k < SCAN_PT; k++) {
        int i = base + k;
        int d = (i < NN) ? sdeg[i] + 1 : 0;   // +1 = self loop
        v[k] = sum;
        sum += d;
    }
    // 2-level exclusive block scan of per-thread sums
    int lane = t & 31, w = t >> 5;
    int s = sum;
    #pragma unroll
    for (int o = 1; o < 32; o <<= 1) {
        int x = __shfl_up_sync(0xffffffffu, s, o);
        if (lane >= o) s += x;
    }
    __shared__ int wt[32];
    if (lane == 31) wt[w] = s;
    __syncthreads();
    if (w == 0) {
        int x = wt[lane];
        #pragma unroll
        for (int o = 1; o < 32; o <<= 1) {
            int y = __shfl_up_sync(0xffffffffu, x, o);
            if (lane >= o) x += y;
        }
        wt[lane] = x;
    }
    __syncthreads();
    int excl = (s - sum) + (w > 0 ? wt[w - 1] : 0);
    #pragma unroll
    for (int k = 0; k < SCAN_PT; k++) {
        int i = base + k;
        if (i < NN) {
            int r = excl + v[k];
            g_rowptr[i] = r;
            g_cursor[i] = r;
        }
    }
    if (t == 0) g_rowptr[NN] = wt[31];
}

__global__ void k_fill(int E) {
    int i = blockIdx.x * 256 + threadIdx.x;
    if (i < E) {
        int p = atomicAdd(&g_cursor[g_dst[i]], 1);
        g_col[p] = g_src[i];
    } else if (i < E + NN) {
        int n = i - E;
        int p = atomicAdd(&g_cursor[n], 1);
        g_col[p] = n;
    }
}

// ---------------- fp16 GEMM, 128x128x32, cp.async double buffered ---------
#define BM 128
#define BN 128
#define BK 32
#define LDA 40      // halfs per A row (32 + 8 pad)
#define LDB 136     // halfs per B row (128 + 8 pad)
#define LDC 132     // floats, epilogue staging
#define A_TILE (BM * LDA)                 // 5120 halfs
#define B_TILE (BK * LDB)                 // 4352 halfs
#define PIPE_HALFS (2 * A_TILE + 2 * B_TILE)    // 18944 halfs = 37888 B
#define GEMM_SMEM (PIPE_HALFS * 2)

__device__ __forceinline__ void gemm_load_stage(
    __half* As, __half* Bs, const __half* A, const __half* B,
    int M, int K, int N, int bm, int bn, int kb, int tid)
{
    #pragma unroll
    for (int i = 0; i < 2; i++) {
        int slot = i * 256 + tid;
        int r = slot >> 2, c8 = slot & 3;
        int grow = bm + r; if (grow > M - 1) grow = M - 1;
        __pipeline_memcpy_async(&As[r * LDA + c8 * 8],
                                &A[(long long)grow * K + kb + c8 * 8], 16);
    }
    #pragma unroll
    for (int i = 0; i < 2; i++) {
        int slot = i * 256 + tid;
        int r = slot >> 4, c8 = slot & 15;
        __pipeline_memcpy_async(&Bs[r * LDB + c8 * 8],
                                &B[(long long)(kb + r) * N + bn + c8 * 8], 16);
    }
}

template <int EPI>
__global__ void __launch_bounds__(256, 2)
gemm_fp16(const __half* __restrict__ A, const __half* __restrict__ B,
          __half* __restrict__ C, int M, int K, int N,
          const float* __restrict__ att_s,
          const float* __restrict__ att_d,
          float* __restrict__ out_s,
          float* __restrict__ out_d)
{
    extern __shared__ __half smem[];
    __half* As[2] = { smem, smem + A_TILE };
    __half* Bs[2] = { smem + 2 * A_TILE, smem + 2 * A_TILE + B_TILE };
    float* Cs = (float*)smem;   // epilogue reuse: 64*LDC*4 = 33792 B <= 37888

    const int tid  = threadIdx.x;
    const int warp = tid >> 5;
    const int wm   = warp >> 2;      // 0..1
    const int wn   = warp & 3;       // 0..3
    const int bm   = blockIdx.y * BM;
    const int bn   = blockIdx.x * BN;

    wmma::fragment<wmma::accumulator, 16, 16, 16, float> acc[4][2];
    #pragma unroll
    for (int i = 0; i < 4; i++)
        #pragma unroll
        for (int j = 0; j < 2; j++)
            wmma::fill_fragment(acc[i][j], 0.0f);

    const int T = K / BK;
    gemm_load_stage(As[0], Bs[0], A, B, M, K, N, bm, bn, 0, tid);
    __pipeline_commit();

    for (int t = 0; t < T; t++) {
        if (t + 1 < T) {
            gemm_load_stage(As[(t + 1) & 1], Bs[(t + 1) & 1], A, B, M, K, N,
                            bm, bn, (t + 1) * BK, tid);
            __pipeline_commit();
            __pipeline_wait_prior(1);
        } else {
            __pipeline_wait_prior(0);
        }
        __syncthreads();

        const __half* at = As[t & 1];
        const __half* bt = Bs[t & 1];
        #pragma unroll
        for (int ks = 0; ks < 2; ks++) {
            wmma::fragment<wmma::matrix_a, 16, 16, 16, __half, wmma::row_major> af[4];
            wmma::fragment<wmma::matrix_b, 16, 16, 16, __half, wmma::row_major> bf[2];
            #pragma unroll
            for (int i = 0; i < 4; i++)
                wmma::load_matrix_sync(af[i], &at[(wm * 64 + i * 16) * LDA + ks * 16], LDA);
            #pragma unroll
            for (int j = 0; j < 2; j++)
                wmma::load_matrix_sync(bf[j], &bt[(ks * 16) * LDB + wn * 32 + j * 16], LDB);
            #pragma unroll
            for (int i = 0; i < 4; i++)
                #pragma unroll
                for (int j = 0; j < 2; j++)
                    wmma::mma_sync(acc[i][j], af[i], bf[j], acc[i][j]);
        }
        __syncthreads();
    }

    // epilogue in two 64-row halves, staged through smem (fp32)
    const int head = blockIdx.x;   // valid for EPI==1 (BN==Hc==128)
    #pragma unroll
    for (int p = 0; p < 2; p++) {
        if (wm == p) {
            #pragma unroll
            for (int i = 0; i < 4; i++)
                #pragma unroll
                for (int j = 0; j < 2; j++)
                    wmma::store_matrix_sync(&Cs[(i * 16) * LDC + wn * 32 + j * 16],
                                            acc[i][j], LDC, wmma::mem_row_major);
        }
        __syncthreads();

        // C writeback (fp16): 64x128 = 2048 half4 slots
        #pragma unroll
        for (int i = 0; i < 8; i++) {
            int slot = i * 256 + tid;
            int r = slot >> 5, c4 = slot & 31;
            int grow = bm + p * 64 + r;
            if (grow < M) {
                float4 v = *(float4*)&Cs[r * LDC + c4 * 4];
                union { uint2 u; __half2 h[2]; } pk;
                pk.h[0] = __floats2half2_rn(v.x, v.y);
                pk.h[1] = __floats2half2_rn(v.z, v.w);
                *(uint2*)&C[(long long)grow * N + bn + c4 * 4] = pk.u;
            }
        }

        // fused attention dots: 4 threads per row, 32 cols each (fp32 from smem)
        {
            int r = tid >> 2, q = tid & 3;
            int grow = bm + p * 64 + r;
            float s = 0.f, d = 0.f;
            const float* crow = &Cs[r * LDC + q * 32];
            const float* avs, *avd;
            if (EPI == 1) { avs = att_s + head * 128 + q * 32; avd = att_d + head * 128 + q * 32; }
            else          { avs = att_s + bn + q * 32;         avd = att_d + bn + q * 32; }
            #pragma unroll
            for (int c = 0; c < 32; c++) {
                float v = crow[c];
                s += v * avs[c];
                d += v * avd[c];
            }
            s += __shfl_down_sync(0xffffffffu, s, 2, 4);
            s += __shfl_down_sync(0xffffffffu, s, 1, 4);
            d += __shfl_down_sync(0xffffffffu, d, 2, 4);
            d += __shfl_down_sync(0xffffffffu, d, 1, 4);
            if (q == 0 && grow < M) {
                if (EPI == 1) {
                    out_s[grow * 4 + head] = s;
                    out_d[grow * 4 + head] = d;
                } else {
                    atomicAdd(&out_s[grow], s);
                    atomicAdd(&out_d[grow], d);
                }
            }
        }
        __syncthreads();
    }
}

// ---------------- segment softmax (warp per dst node) ----------------
__device__ __forceinline__ float lrelu(float v) { return v > 0.f ? v : 0.2f * v; }

__global__ void k_softmax1() {
    int warp = threadIdx.x >> 5, lane = threadIdx.x & 31;
    int n = blockIdx.x * 8 + warp;
    int s0 = g_rowptr[n], s1 = g_rowptr[n + 1];
    float4 ad = *(const float4*)&g_adst1[n * 4];
    float m0 = -1e30f, m1 = -1e30f, m2 = -1e30f, m3 = -1e30f;
    for (int j = s0 + lane; j < s1; j += 32) {
        float4 as = *(const float4*)&g_asrc1[g_col[j] * 4];
        m0 = fmaxf(m0, lrelu(as.x + ad.x));
        m1 = fmaxf(m1, lrelu(as.y + ad.y));
        m2 = fmaxf(m2, lrelu(as.z + ad.z));
        m3 = fmaxf(m3, lrelu(as.w + ad.w));
    }
    #pragma unroll
    for (int o = 16; o; o >>= 1) {
        m0 = fmaxf(m0, __shfl_xor_sync(0xffffffffu, m0, o));
        m1 = fmaxf(m1, __shfl_xor_sync(0xffffffffu, m1, o));
        m2 = fmaxf(m2, __shfl_xor_sync(0xffffffffu, m2, o));
        m3 = fmaxf(m3, __shfl_xor_sync(0xffffffffu, m3, o));
    }
    float t0 = 0.f, t1 = 0.f, t2 = 0.f, t3 = 0.f;
    for (int j = s0 + lane; j < s1; j += 32) {
        float4 as = *(const float4*)&g_asrc1[g_col[j] * 4];
        float4 p;
        p.x = __expf(lrelu(as.x + ad.x) - m0); t0 += p.x;
        p.y = __expf(lrelu(as.y + ad.y) - m1); t1 += p.y;
        p.z = __expf(lrelu(as.z + ad.z) - m2); t2 += p.z;
        p.w = __expf(lrelu(as.w + ad.w) - m3); t3 += p.w;
        *(float4*)&g_alpha1[j * 4] = p;
    }
    #pragma unroll
    for (int o = 16; o; o >>= 1) {
        t0 += __shfl_xor_sync(0xffffffffu, t0, o);
        t1 += __shfl_xor_sync(0xffffffffu, t1, o);
        t2 += __shfl_xor_sync(0xffffffffu, t2, o);
        t3 += __shfl_xor_sync(0xffffffffu, t3, o);
    }
    if (lane == 0) {
        float4 t = make_float4(t0, t1, t2, t3);
        *(float4*)&g_den1[n * 4] = t;
    }
}

__global__ void k_softmax2() {
    int warp = threadIdx.x >> 5, lane = threadIdx.x & 31;
    int n = blockIdx.x * 8 + warp;
    int s0 = g_rowptr[n], s1 = g_rowptr[n + 1];
    float ad = g_adst2[n];
    float m = -1e30f;
    for (int j = s0 + lane; j < s1; j += 32)
        m = fmaxf(m, lrelu(g_asrc2[g_col[j]] + ad));
    #pragma unroll
    for (int o = 16; o; o >>= 1) m = fmaxf(m, __shfl_xor_sync(0xffffffffu, m, o));
    float t = 0.f;
    for (int j = s0 + lane; j < s1; j += 32) {
        float p = __expf(lrelu(g_asrc2[g_col[j]] + ad) - m);
        t += p;
        g_alpha2[j] = p;
    }
    #pragma unroll
    for (int o = 16; o; o >>= 1) t += __shfl_xor_sync(0xffffffffu, t, o);
    if (lane == 0) g_den2[n] = t;
}

// ------------- CSR aggregation layer 1 (fp16 gather) + bias + GELU --------
__global__ void k_aggregate1(const float* __restrict__ b1) {
    int wid = blockIdx.x * 8 + (threadIdx.x >> 5);
    int n = wid >> 2, h = wid & 3, lane = threadIdx.x & 31;
    int s0 = g_rowptr[n], s1 = g_rowptr[n + 1];
    int off = h * 128 + lane * 4;
    const __half* hb = g_h1h + off;
    float4 acc0 = make_float4(0.f, 0.f, 0.f, 0.f);
    float4 acc1 = make_float4(0.f, 0.f, 0.f, 0.f);
    int j = s0;
    for (; j + 3 < s1; j += 4) {
        int c0 = g_col[j],     c1 = g_col[j + 1];
        int c2 = g_col[j + 2], c3 = g_col[j + 3];
        float a0 = g_alpha1[j * 4 + h],       a1 = g_alpha1[(j + 1) * 4 + h];
        float a2 = g_alpha1[(j + 2) * 4 + h], a3 = g_alpha1[(j + 3) * 4 + h];
        uint2 r0 = *(const uint2*)&hb[c0 * 512];
        uint2 r1 = *(const uint2*)&hb[c1 * 512];
        uint2 r2 = *(const uint2*)&hb[c2 * 512];
        uint2 r3 = *(const uint2*)&hb[c3 * 512];
        float2 v0a = __half22float2(*(__half2*)&r0.x), v0b = __half22float2(*(__half2*)&r0.y);
        float2 v1a = __half22float2(*(__half2*)&r1.x), v1b = __half22float2(*(__half2*)&r1.y);
        float2 v2a = __half22float2(*(__half2*)&r2.x), v2b = __half22float2(*(__half2*)&r2.y);
        float2 v3a = __half22float2(*(__half2*)&r3.x), v3b = __half22float2(*(__half2*)&r3.y);
        acc0.x += a0 * v0a.x + a2 * v2a.x;  acc1.x += a1 * v1a.x + a3 * v3a.x;
        acc0.y += a0 * v0a.y + a2 * v2a.y;  acc1.y += a1 * v1a.y + a3 * v3a.y;
        acc0.z += a0 * v0b.x + a2 * v2b.x;  acc1.z += a1 * v1b.x + a3 * v3b.x;
        acc0.w += a0 * v0b.y + a2 * v2b.y;  acc1.w += a1 * v1b.y + a3 * v3b.y;
    }
    for (; j < s1; j++) {
        int c0 = g_col[j];
        float a0 = g_alpha1[j * 4 + h];
        uint2 r0 = *(const uint2*)&hb[c0 * 512];
        float2 v0a = __half22float2(*(__half2*)&r0.x), v0b = __half22float2(*(__half2*)&r0.y);
        acc0.x += a0 * v0a.x; acc0.y += a0 * v0a.y;
        acc0.z += a0 * v0b.x; acc0.w += a0 * v0b.y;
    }
    float inv = 1.0f / g_den1[n * 4 + h];
    float4 bb = *(const float4*)&b1[off];
    float4 y;
    y.x = (acc0.x + acc1.x) * inv + bb.x;
    y.y = (acc0.y + acc1.y) * inv + bb.y;
    y.z = (acc0.z + acc1.z) * inv + bb.z;
    y.w = (acc0.w + acc1.w) * inv + bb.w;
    y.x = y.x * normcdff(y.x);
    y.y = y.y * normcdff(y.y);
    y.z = y.z * normcdff(y.z);
    y.w = y.w * normcdff(y.w);
    union { uint2 u; __half2 h2[2]; } pk;
    pk.h2[0] = __floats2half2_rn(y.x, y.y);
    pk.h2[1] = __floats2half2_rn(y.z, y.w);
    *(uint2*)&g_out1h[n * 512 + off] = pk.u;
}

__global__ void k_aggregate2(const float* __restrict__ b2, float* __restrict__ out) {
    int wid = blockIdx.x * 8 + (threadIdx.x >> 5);
    int n = wid, lane = threadIdx.x & 31;
    int s0 = g_rowptr[n], s1 = g_rowptr[n + 1];
    float4 acc0 = make_float4(0.f, 0.f, 0.f, 0.f);
    float4 acc1 = make_float4(0.f, 0.f, 0.f, 0.f);
    const __half* hb = g_h2h + lane * 4;
    for (int j = s0; j < s1; j++) {
        int c = g_col[j];
        float a = g_alpha2[j];
        uint2 r0 = *(const uint2*)&hb[c * 256];
        uint2 r1 = *(const uint2*)&hb[c * 256 + 128];
        float2 u0 = __half22float2(*(__half2*)&r0.x), u1 = __half22float2(*(__half2*)&r0.y);
        float2 w0 = __half22float2(*(__half2*)&r1.x), w1 = __half22float2(*(__half2*)&r1.y);
        acc0.x += a * u0.x; acc0.y += a * u0.y; acc0.z += a * u1.x; acc0.w += a * u1.y;
        acc1.x += a * w0.x; acc1.y += a * w0.y; acc1.z += a * w1.x; acc1.w += a * w1.y;
    }
    float inv = 1.0f / g_den2[n];
    float4 bb0 = *(const float4*)&b2[lane * 4];
    float4 bb1 = *(const float4*)&b2[128 + lane * 4];
    float4 o0, o1;
    o0.x = acc0.x * inv + bb0.x; o0.y = acc0.y * inv + bb0.y;
    o0.z = acc0.z * inv + bb0.z; o0.w = acc0.w * inv + bb0.w;
    o1.x = acc1.x * inv + bb1.x; o1.y = acc1.y * inv + bb1.y;
    o1.z = acc1.z * inv + bb1.z; o1.w = acc1.w * inv + bb1.w;
    *(float4*)&out[n * 256 + lane * 4] = o0;
    *(float4*)&out[n * 256 + 128 + lane * 4] = o1;
}

// ---------------- host launcher ----------------
extern "C" void kernel_launch(void* const* d_in, const int* in_sizes, int n_in,
                              void* d_out, int out_size)
{
    const float* x   = (const float*)d_in[0];
    const void*  ei  = d_in[1];
    const float* W1  = (const float*)d_in[2];
    const float* as1 = (const float*)d_in[3];
    const float* ad1 = (const float*)d_in[4];
    const float* b1  = (const float*)d_in[5];
    const float* W2  = (const float*)d_in[6];
    const float* as2 = (const float*)d_in[7];
    const float* ad2 = (const float*)d_in[8];
    const float* b2  = (const float*)d_in[9];
    float*       out = (float*)d_out;
    const int E = in_sizes[1] / 2;   // 320000

    __half *p_xh, *p_W1h, *p_W2h, *p_h1, *p_out1h, *p_h2;
    float *p_as1, *p_ad1, *p_as2, *p_ad2;
    cudaGetSymbolAddress((void**)&p_xh,    g_xh);
    cudaGetSymbolAddress((void**)&p_W1h,   g_W1h);
    cudaGetSymbolAddress((void**)&p_W2h,   g_W2h);
    cudaGetSymbolAddress((void**)&p_h1,    g_h1h);
    cudaGetSymbolAddress((void**)&p_out1h, g_out1h);
    cudaGetSymbolAddress((void**)&p_h2,    g_h2h);
    cudaGetSymbolAddress((void**)&p_as1,   g_asrc1);
    cudaGetSymbolAddress((void**)&p_ad1,   g_adst1);
    cudaGetSymbolAddress((void**)&p_as2,   g_asrc2);
    cudaGetSymbolAddress((void**)&p_ad2,   g_adst2);

    cudaFuncSetAttribute(gemm_fp16<1>, cudaFuncAttributeMaxDynamicSharedMemorySize, GEMM_SMEM);
    cudaFuncSetAttribute(gemm_fp16<2>, cudaFuncAttributeMaxDynamicSharedMemorySize, GEMM_SMEM);
    cudaFuncSetAttribute(k_scan, cudaFuncAttributeMaxDynamicSharedMemorySize, SCAN_SMEM);

    // kernel launch order chosen so gemm_fp16<1> is the 4th launch (ncu window)
    k_detect_zero<<<(NN + 255) / 256, 256>>>(ei);
    k_f2h<<<((XH_N + W1_N + W2_N) / 4 + 255) / 256, 256>>>(x, W1, W2);
    k_convert_hist<<<(E + 255) / 256, 256>>>(ei, E);

    gemm_fp16<1><<<dim3(512 / BN, (NN + BM - 1) / BM), 256, GEMM_SMEM>>>(
        p_xh, p_W1h, p_h1, NN, 256, 512, as1, ad1, p_as1, p_ad1);

    k_scan<<<1, 1024, SCAN_SMEM>>>();
    k_fill<<<(E + NN + 255) / 256, 256>>>(E);
    k_softmax1<<<NN / 8, 256>>>();
    k_aggregate1<<<(NN * 4) / 8, 256>>>(b1);

    // layer 2
    cudaMemsetAsync(p_as2, 0, NN * sizeof(float), 0);
    cudaMemsetAsync(p_ad2, 0, NN * sizeof(float), 0);
    gemm_fp16<2><<<dim3(256 / BN, (NN + BM - 1) / BM), 256, GEMM_SMEM>>>(
        p_out1h, p_W2h, p_h2, NN, 512, 256, as2, ad2, p_as2, p_ad2);

    k_softmax2<<<NN / 8, 256>>>();
    k_aggregate2<<<NN / 8, 256>>>(b2, out);
}

// round 9
// speedup vs baseline: 1.1579x; 1.1579x over previous
#include <cuda_runtime.h>
#include <cuda_pipeline.h>
#include <cuda_fp16.h>
#include <mma.h>
#include <math.h>

using namespace nvcuda;

#define NN 20000
#define EE 320000
#define TE (EE + NN)   // edges + self loops

// ---------------- device scratch (no allocations allowed) ----------------
__device__ __half g_xh[NN * 256];     // x in fp16 (GEMM1 A)
__device__ __half g_W1h[256 * 512];   // W1 in fp16
__device__ __half g_W2h[512 * 256];   // W2 in fp16
__device__ __half g_h1h[NN * 512];    // layer1 linear output, fp16 (gather-only)
__device__ __half g_out1h[NN * 512];  // layer1 aggregated+bias+gelu, fp16 (GEMM2 A)
__device__ __half g_h2h[NN * 256];    // layer2 linear output, fp16 (gather-only)
__device__ float  g_asrc1[NN * 4];
__device__ float  g_adst1[NN * 4];
__device__ float  g_asrc2[NN];
__device__ float  g_adst2[NN];
__device__ float  g_den1[NN * 4];
__device__ float  g_den2[NN];
__device__ float  g_alpha1[TE * 4];   // unnormalized exp weights, CSR order
__device__ float  g_alpha2[TE];
__device__ int    g_rowptr[NN + 1];
__device__ int    g_col[TE];          // src node per CSR slot
__device__ int    g_deg[NN];          // edge-only indegree (self loop added in scan)
__device__ int    g_cursor[NN];
__device__ int    g_src[EE];
__device__ int    g_dst[EE];
__device__ int    g_is64;

// -------- detect edge dtype (thread 0) + zero degree array (whole grid) ----
__global__ void k_detect_zero(const void* ei) {
    int i = blockIdx.x * 256 + threadIdx.x;
    if (i < NN) g_deg[i] = 0;
    if (i == 0) {
        const unsigned long long* p = (const unsigned long long*)ei;
        int ok64 = 1;
        for (int k = 0; k < 4; k++) if (p[k] >= (unsigned long long)NN) ok64 = 0;
        g_is64 = ok64;
    }
}

// ---------------- fp32 -> fp16 conversions (x, W1, W2 in one launch) ------
#define XH_N (NN * 256)
#define W1_N (256 * 512)
#define W2_N (512 * 256)
__global__ void k_f2h(const float* __restrict__ x, const float* __restrict__ W1,
                      const float* __restrict__ W2)
{
    int i = blockIdx.x * 256 + threadIdx.x;    // one float4 per thread
    int tot4 = (XH_N + W1_N + W2_N) / 4;
    if (i >= tot4) return;
    const float* src;
    __half* dst;
    int off;
    if (i < XH_N / 4)                 { src = x;  dst = g_xh;  off = i; }
    else if (i < (XH_N + W1_N) / 4)   { src = W1; dst = g_W1h; off = i - XH_N / 4; }
    else                              { src = W2; dst = g_W2h; off = i - (XH_N + W1_N) / 4; }
    float4 v = *(const float4*)&src[off * 4];
    union { uint2 u; __half2 h[2]; } pk;
    pk.h[0] = __floats2half2_rn(v.x, v.y);
    pk.h[1] = __floats2half2_rn(v.z, v.w);
    *(uint2*)&dst[off * 4] = pk.u;
}

// ---------------- edge convert + histogram ----------------
__global__ void k_convert_hist(const void* ei, int E) {
    int i = blockIdx.x * 256 + threadIdx.x;
    if (i >= E) return;
    int s, d;
    if (g_is64) {
        const long long* p = (const long long*)ei;
        s = (int)p[i]; d = (int)p[E + i];
    } else {
        const int* p = (const int*)ei;
        s = p[i]; d = p[E + i];
    }
    s = min(max(s, 0), NN - 1);
    d = min(max(d, 0), NN - 1);
    g_src[i] = s; g_dst[i] = d;
    atomicAdd(&g_deg[d], 1);
}

// ------------- exclusive scan: smem-staged, 1024 thr x 20 elems ------------
#define SCAN_PT 20                    // 1024*20 = 20480 >= NN
#define SCAN_SMEM (20480 * 4)         // 80 KB dynamic
__global__ void k_scan() {
    extern __shared__ int sdeg[];     // 20480 ints
    int t = threadIdx.x;
    #pragma unroll
    for (int i = 0; i < 5; i++) {
        int idx = i * 1024 + t;       // int4 index
        if (idx < NN / 4) {
            *(int4*)&sdeg[idx * 4] = *(const int4*)&g_deg[idx * 4];
        } else {
            *(int4*)&sdeg[idx * 4] = make_int4(0, 0, 0, 0);
        }
    }
    __syncthreads();

    int base = t * SCAN_PT;
    int v[SCAN_PT];
    int sum = 0;
    #pragma unroll
    for (int k = 0; k < SCAN_PT; k++) {
        int i = base + k;
        int d = (i < NN) ? sdeg[i] + 1 : 0;   // +1 = self loop
        v[k] = sum;
        sum += d;
    }
    int lane = t & 31, w = t >> 5;
    int s = sum;
    #pragma unroll
    for (int o = 1; o < 32; o <<= 1) {
        int x = __shfl_up_sync(0xffffffffu, s, o);
        if (lane >= o) s += x;
    }
    __shared__ int wt[32];
    if (lane == 31) wt[w] = s;
    __syncthreads();
    if (w == 0) {
        int x = wt[lane];
        #pragma unroll
        for (int o = 1; o < 32; o <<= 1) {
            int y = __shfl_up_sync(0xffffffffu, x, o);
            if (lane >= o) x += y;
        }
        wt[lane] = x;
    }
    __syncthreads();
    int excl = (s - sum) + (w > 0 ? wt[w - 1] : 0);
    #pragma unroll
    for (int k = 0; k < SCAN_PT; k++) {
        int i = base + k;
        if (i < NN) {
            int r = excl + v[k];
            g_rowptr[i] = r;
            g_cursor[i] = r;
        }
    }
    if (t == 0) g_rowptr[NN] = wt[31];
}

__global__ void k_fill(int E) {
    int i = blockIdx.x * 256 + threadIdx.x;
    if (i < E) {
        int p = atomicAdd(&g_cursor[g_dst[i]], 1);
        g_col[p] = g_src[i];
    } else if (i < E + NN) {
        int n = i - E;
        int p = atomicAdd(&g_cursor[n], 1);
        g_col[p] = n;
    }
}

// ---------------- fp16 GEMM, 128x128x32, cp.async double buffered ---------
#define BM 128
#define BN 128
#define BK 32
#define LDA 40      // halfs per A row (32 + 8 pad)
#define LDB 136     // halfs per B row (128 + 8 pad)
#define LDC 132     // floats, epilogue staging
#define A_TILE (BM * LDA)                 // 5120 halfs
#define B_TILE (BK * LDB)                 // 4352 halfs
#define PIPE_HALFS (2 * A_TILE + 2 * B_TILE)    // 18944 halfs = 37888 B
#define GEMM_SMEM (PIPE_HALFS * 2)

__device__ __forceinline__ void gemm_load_stage(
    __half* As, __half* Bs, const __half* A, const __half* B,
    int M, int K, int N, int bm, int bn, int kb, int tid)
{
    #pragma unroll
    for (int i = 0; i < 2; i++) {
        int slot = i * 256 + tid;
        int r = slot >> 2, c8 = slot & 3;
        int grow = bm + r; if (grow > M - 1) grow = M - 1;
        __pipeline_memcpy_async(&As[r * LDA + c8 * 8],
                                &A[(long long)grow * K + kb + c8 * 8], 16);
    }
    #pragma unroll
    for (int i = 0; i < 2; i++) {
        int slot = i * 256 + tid;
        int r = slot >> 4, c8 = slot & 15;
        __pipeline_memcpy_async(&Bs[r * LDB + c8 * 8],
                                &B[(long long)(kb + r) * N + bn + c8 * 8], 16);
    }
}

template <int EPI>
__global__ void __launch_bounds__(256, 2)
gemm_fp16(const __half* __restrict__ A, const __half* __restrict__ B,
          __half* __restrict__ C, int M, int K, int N,
          const float* __restrict__ att_s,
          const float* __restrict__ att_d,
          float* __restrict__ out_s,
          float* __restrict__ out_d)
{
    extern __shared__ __half smem[];
    __half* As[2] = { smem, smem + A_TILE };
    __half* Bs[2] = { smem + 2 * A_TILE, smem + 2 * A_TILE + B_TILE };
    float* Cs = (float*)smem;   // epilogue reuse: 64*LDC*4 = 33792 B <= 37888

    const int tid  = threadIdx.x;
    const int warp = tid >> 5;
    const int wm   = warp >> 2;      // 0..1
    const int wn   = warp & 3;       // 0..3
    const int bm   = blockIdx.y * BM;
    const int bn   = blockIdx.x * BN;

    wmma::fragment<wmma::accumulator, 16, 16, 16, float> acc[4][2];
    #pragma unroll
    for (int i = 0; i < 4; i++)
        #pragma unroll
        for (int j = 0; j < 2; j++)
            wmma::fill_fragment(acc[i][j], 0.0f);

    const int T = K / BK;
    gemm_load_stage(As[0], Bs[0], A, B, M, K, N, bm, bn, 0, tid);
    __pipeline_commit();

    for (int t = 0; t < T; t++) {
        if (t + 1 < T) {
            gemm_load_stage(As[(t + 1) & 1], Bs[(t + 1) & 1], A, B, M, K, N,
                            bm, bn, (t + 1) * BK, tid);
            __pipeline_commit();
            __pipeline_wait_prior(1);
        } else {
            __pipeline_wait_prior(0);
        }
        __syncthreads();

        const __half* at = As[t & 1];
        const __half* bt = Bs[t & 1];
        #pragma unroll
        for (int ks = 0; ks < 2; ks++) {
            wmma::fragment<wmma::matrix_a, 16, 16, 16, __half, wmma::row_major> af[4];
            wmma::fragment<wmma::matrix_b, 16, 16, 16, __half, wmma::row_major> bf[2];
            #pragma unroll
            for (int i = 0; i < 4; i++)
                wmma::load_matrix_sync(af[i], &at[(wm * 64 + i * 16) * LDA + ks * 16], LDA);
            #pragma unroll
            for (int j = 0; j < 2; j++)
                wmma::load_matrix_sync(bf[j], &bt[(ks * 16) * LDB + wn * 32 + j * 16], LDB);
            #pragma unroll
            for (int i = 0; i < 4; i++)
                #pragma unroll
                for (int j = 0; j < 2; j++)
                    wmma::mma_sync(acc[i][j], af[i], bf[j], acc[i][j]);
        }
        __syncthreads();
    }

    // epilogue in two 64-row halves, staged through smem (fp32)
    const int head = blockIdx.x;   // valid for EPI==1 (BN==Hc==128)
    #pragma unroll
    for (int p = 0; p < 2; p++) {
        if (wm == p) {
            #pragma unroll
            for (int i = 0; i < 4; i++)
                #pragma unroll
                for (int j = 0; j < 2; j++)
                    wmma::store_matrix_sync(&Cs[(i * 16) * LDC + wn * 32 + j * 16],
                                            acc[i][j], LDC, wmma::mem_row_major);
        }
        __syncthreads();

        // C writeback (fp16): 64x128 = 2048 half4 slots
        #pragma unroll
        for (int i = 0; i < 8; i++) {
            int slot = i * 256 + tid;
            int r = slot >> 5, c4 = slot & 31;
            int grow = bm + p * 64 + r;
            if (grow < M) {
                float4 v = *(float4*)&Cs[r * LDC + c4 * 4];
                union { uint2 u; __half2 h[2]; } pk;
                pk.h[0] = __floats2half2_rn(v.x, v.y);
                pk.h[1] = __floats2half2_rn(v.z, v.w);
                *(uint2*)&C[(long long)grow * N + bn + c4 * 4] = pk.u;
            }
        }

        // fused attention dots: 4 threads per row, 32 cols each (fp32 from smem)
        {
            int r = tid >> 2, q = tid & 3;
            int grow = bm + p * 64 + r;
            float s = 0.f, d = 0.f;
            const float* crow = &Cs[r * LDC + q * 32];
            const float* avs, *avd;
            if (EPI == 1) { avs = att_s + head * 128 + q * 32; avd = att_d + head * 128 + q * 32; }
            else          { avs = att_s + bn + q * 32;         avd = att_d + bn + q * 32; }
            #pragma unroll
            for (int c = 0; c < 32; c++) {
                float v = crow[c];
                s += v * avs[c];
                d += v * avd[c];
            }
            s += __shfl_down_sync(0xffffffffu, s, 2, 4);
            s += __shfl_down_sync(0xffffffffu, s, 1, 4);
            d += __shfl_down_sync(0xffffffffu, d, 2, 4);
            d += __shfl_down_sync(0xffffffffu, d, 1, 4);
            if (q == 0 && grow < M) {
                if (EPI == 1) {
                    out_s[grow * 4 + head] = s;
                    out_d[grow * 4 + head] = d;
                } else {
                    atomicAdd(&out_s[grow], s);
                    atomicAdd(&out_d[grow], d);
                }
            }
        }
        __syncthreads();
    }
}

// ---------------- segment softmax (warp per dst node) ----------------
__device__ __forceinline__ float lrelu(float v) { return v > 0.f ? v : 0.2f * v; }

__global__ void k_softmax1() {
    int warp = threadIdx.x >> 5, lane = threadIdx.x & 31;
    int n = blockIdx.x * 8 + warp;
    int s0 = g_rowptr[n], s1 = g_rowptr[n + 1];
    float4 ad = *(const float4*)&g_adst1[n * 4];
    float m0 = -1e30f, m1 = -1e30f, m2 = -1e30f, m3 = -1e30f;
    for (int j = s0 + lane; j < s1; j += 32) {
        float4 as = *(const float4*)&g_asrc1[g_col[j] * 4];
        m0 = fmaxf(m0, lrelu(as.x + ad.x));
        m1 = fmaxf(m1, lrelu(as.y + ad.y));
        m2 = fmaxf(m2, lrelu(as.z + ad.z));
        m3 = fmaxf(m3, lrelu(as.w + ad.w));
    }
    #pragma unroll
    for (int o = 16; o; o >>= 1) {
        m0 = fmaxf(m0, __shfl_xor_sync(0xffffffffu, m0, o));
        m1 = fmaxf(m1, __shfl_xor_sync(0xffffffffu, m1, o));
        m2 = fmaxf(m2, __shfl_xor_sync(0xffffffffu, m2, o));
        m3 = fmaxf(m3, __shfl_xor_sync(0xffffffffu, m3, o));
    }
    float t0 = 0.f, t1 = 0.f, t2 = 0.f, t3 = 0.f;
    for (int j = s0 + lane; j < s1; j += 32) {
        float4 as = *(const float4*)&g_asrc1[g_col[j] * 4];
        float4 p;
        p.x = __expf(lrelu(as.x + ad.x) - m0); t0 += p.x;
        p.y = __expf(lrelu(as.y + ad.y) - m1); t1 += p.y;
        p.z = __expf(lrelu(as.z + ad.z) - m2); t2 += p.z;
        p.w = __expf(lrelu(as.w + ad.w) - m3); t3 += p.w;
        *(float4*)&g_alpha1[j * 4] = p;
    }
    #pragma unroll
    for (int o = 16; o; o >>= 1) {
        t0 += __shfl_xor_sync(0xffffffffu, t0, o);
        t1 += __shfl_xor_sync(0xffffffffu, t1, o);
        t2 += __shfl_xor_sync(0xffffffffu, t2, o);
        t3 += __shfl_xor_sync(0xffffffffu, t3, o);
    }
    if (lane == 0) {
        float4 t = make_float4(t0, t1, t2, t3);
        *(float4*)&g_den1[n * 4] = t;
    }
}

__global__ void k_softmax2() {
    int warp = threadIdx.x >> 5, lane = threadIdx.x & 31;
    int n = blockIdx.x * 8 + warp;
    int s0 = g_rowptr[n], s1 = g_rowptr[n + 1];
    float ad = g_adst2[n];
    float m = -1e30f;
    for (int j = s0 + lane; j < s1; j += 32)
        m = fmaxf(m, lrelu(g_asrc2[g_col[j]] + ad));
    #pragma unroll
    for (int o = 16; o; o >>= 1) m = fmaxf(m, __shfl_xor_sync(0xffffffffu, m, o));
    float t = 0.f;
    for (int j = s0 + lane; j < s1; j += 32) {
        float p = __expf(lrelu(g_asrc2[g_col[j]] + ad) - m);
        t += p;
        g_alpha2[j] = p;
    }
    #pragma unroll
    for (int o = 16; o; o >>= 1) t += __shfl_xor_sync(0xffffffffu, t, o);
    if (lane == 0) g_den2[n] = t;
}

// ------------- CSR aggregation layer 1 (fp16 gather) + bias + GELU --------
__global__ void k_aggregate1(const float* __restrict__ b1) {
    int wid = blockIdx.x * 8 + (threadIdx.x >> 5);
    int n = wid >> 2, h = wid & 3, lane = threadIdx.x & 31;
    int s0 = g_rowptr[n], s1 = g_rowptr[n + 1];
    int off = h * 128 + lane * 4;
    const __half* hb = g_h1h + off;
    float4 acc0 = make_float4(0.f, 0.f, 0.f, 0.f);
    float4 acc1 = make_float4(0.f, 0.f, 0.f, 0.f);
    int j = s0;
    for (; j + 3 < s1; j += 4) {
        int c0 = g_col[j],     c1 = g_col[j + 1];
        int c2 = g_col[j + 2], c3 = g_col[j + 3];
        float a0 = g_alpha1[j * 4 + h],       a1 = g_alpha1[(j + 1) * 4 + h];
        float a2 = g_alpha1[(j + 2) * 4 + h], a3 = g_alpha1[(j + 3) * 4 + h];
        uint2 r0 = *(const uint2*)&hb[c0 * 512];
        uint2 r1 = *(const uint2*)&hb[c1 * 512];
        uint2 r2 = *(const uint2*)&hb[c2 * 512];
        uint2 r3 = *(const uint2*)&hb[c3 * 512];
        float2 v0a = __half22float2(*(__half2*)&r0.x), v0b = __half22float2(*(__half2*)&r0.y);
        float2 v1a = __half22float2(*(__half2*)&r1.x), v1b = __half22float2(*(__half2*)&r1.y);
        float2 v2a = __half22float2(*(__half2*)&r2.x), v2b = __half22float2(*(__half2*)&r2.y);
        float2 v3a = __half22float2(*(__half2*)&r3.x), v3b = __half22float2(*(__half2*)&r3.y);
        acc0.x += a0 * v0a.x + a2 * v2a.x;  acc1.x += a1 * v1a.x + a3 * v3a.x;
        acc0.y += a0 * v0a.y + a2 * v2a.y;  acc1.y += a1 * v1a.y + a3 * v3a.y;
        acc0.z += a0 * v0b.x + a2 * v2b.x;  acc1.z += a1 * v1b.x + a3 * v3b.x;
        acc0.w += a0 * v0b.y + a2 * v2b.y;  acc1.w += a1 * v1b.y + a3 * v3b.y;
    }
    for (; j < s1; j++) {
        int c0 = g_col[j];
        float a0 = g_alpha1[j * 4 + h];
        uint2 r0 = *(const uint2*)&hb[c0 * 512];
        float2 v0a = __half22float2(*(__half2*)&r0.x), v0b = __half22float2(*(__half2*)&r0.y);
        acc0.x += a0 * v0a.x; acc0.y += a0 * v0a.y;
        acc0.z += a0 * v0b.x; acc0.w += a0 * v0b.y;
    }
    float inv = 1.0f / g_den1[n * 4 + h];
    float4 bb = *(const float4*)&b1[off];
    float4 y;
    y.x = (acc0.x + acc1.x) * inv + bb.x;
    y.y = (acc0.y + acc1.y) * inv + bb.y;
    y.z = (acc0.z + acc1.z) * inv + bb.z;
    y.w = (acc0.w + acc1.w) * inv + bb.w;
    y.x = y.x * normcdff(y.x);
    y.y = y.y * normcdff(y.y);
    y.z = y.z * normcdff(y.z);
    y.w = y.w * normcdff(y.w);
    union { uint2 u; __half2 h2[2]; } pk;
    pk.h2[0] = __floats2half2_rn(y.x, y.y);
    pk.h2[1] = __floats2half2_rn(y.z, y.w);
    *(uint2*)&g_out1h[n * 512 + off] = pk.u;
}

__global__ void k_aggregate2(const float* __restrict__ b2, float* __restrict__ out) {
    int wid = blockIdx.x * 8 + (threadIdx.x >> 5);
    int n = wid, lane = threadIdx.x & 31;
    int s0 = g_rowptr[n], s1 = g_rowptr[n + 1];
    float4 acc0 = make_float4(0.f, 0.f, 0.f, 0.f);
    float4 acc1 = make_float4(0.f, 0.f, 0.f, 0.f);
    const __half* hb = g_h2h + lane * 4;
    for (int j = s0; j < s1; j++) {
        int c = g_col[j];
        float a = g_alpha2[j];
        uint2 r0 = *(const uint2*)&hb[c * 256];
        uint2 r1 = *(const uint2*)&hb[c * 256 + 128];
        float2 u0 = __half22float2(*(__half2*)&r0.x), u1 = __half22float2(*(__half2*)&r0.y);
        float2 w0 = __half22float2(*(__half2*)&r1.x), w1 = __half22float2(*(__half2*)&r1.y);
        acc0.x += a * u0.x; acc0.y += a * u0.y; acc0.z += a * u1.x; acc0.w += a * u1.y;
        acc1.x += a * w0.x; acc1.y += a * w0.y; acc1.z += a * w1.x; acc1.w += a * w1.y;
    }
    float inv = 1.0f / g_den2[n];
    float4 bb0 = *(const float4*)&b2[lane * 4];
    float4 bb1 = *(const float4*)&b2[128 + lane * 4];
    float4 o0, o1;
    o0.x = acc0.x * inv + bb0.x; o0.y = acc0.y * inv + bb0.y;
    o0.z = acc0.z * inv + bb0.z; o0.w = acc0.w * inv + bb0.w;
    o1.x = acc1.x * inv + bb1.x; o1.y = acc1.y * inv + bb1.y;
    o1.z = acc1.z * inv + bb1.z; o1.w = acc1.w * inv + bb1.w;
    *(float4*)&out[n * 256 + lane * 4] = o0;
    *(float4*)&out[n * 256 + 128 + lane * 4] = o1;
}

// ---------------- host launcher ----------------
extern "C" void kernel_launch(void* const* d_in, const int* in_sizes, int n_in,
                              void* d_out, int out_size)
{
    const float* x   = (const float*)d_in[0];
    const void*  ei  = d_in[1];
    const float* W1  = (const float*)d_in[2];
    const float* as1 = (const float*)d_in[3];
    const float* ad1 = (const float*)d_in[4];
    const float* b1  = (const float*)d_in[5];
    const float* W2  = (const float*)d_in[6];
    const float* as2 = (const float*)d_in[7];
    const float* ad2 = (const float*)d_in[8];
    const float* b2  = (const float*)d_in[9];
    float*       out = (float*)d_out;
    const int E = in_sizes[1] / 2;   // 320000

    __half *p_xh, *p_W1h, *p_W2h, *p_h1, *p_out1h, *p_h2;
    float *p_as1, *p_ad1, *p_as2, *p_ad2;
    cudaGetSymbolAddress((void**)&p_xh,    g_xh);
    cudaGetSymbolAddress((void**)&p_W1h,   g_W1h);
    cudaGetSymbolAddress((void**)&p_W2h,   g_W2h);
    cudaGetSymbolAddress((void**)&p_h1,    g_h1h);
    cudaGetSymbolAddress((void**)&p_out1h, g_out1h);
    cudaGetSymbolAddress((void**)&p_h2,    g_h2h);
    cudaGetSymbolAddress((void**)&p_as1,   g_asrc1);
    cudaGetSymbolAddress((void**)&p_ad1,   g_adst1);
    cudaGetSymbolAddress((void**)&p_as2,   g_asrc2);
    cudaGetSymbolAddress((void**)&p_ad2,   g_adst2);

    cudaFuncSetAttribute(gemm_fp16<1>, cudaFuncAttributeMaxDynamicSharedMemorySize, GEMM_SMEM);
    cudaFuncSetAttribute(gemm_fp16<2>, cudaFuncAttributeMaxDynamicSharedMemorySize, GEMM_SMEM);
    cudaFuncSetAttribute(k_scan, cudaFuncAttributeMaxDynamicSharedMemorySize, SCAN_SMEM);

    // fork: CSR chain on s2, concurrent with f2h + gemm1 on the main stream
    static cudaStream_t s2 = nullptr;
    static cudaEvent_t e0 = nullptr, e1 = nullptr;
    if (!s2) {
        cudaStreamCreateWithFlags(&s2, cudaStreamNonBlocking);
        cudaEventCreateWithFlags(&e0, cudaEventDisableTiming);
        cudaEventCreateWithFlags(&e1, cudaEventDisableTiming);
    }

    cudaEventRecord(e0, 0);
    cudaStreamWaitEvent(s2, e0, 0);

    // s2: full CSR build (independent of GEMM1 inputs)
    k_detect_zero<<<(NN + 255) / 256, 256, 0, s2>>>(ei);
    k_convert_hist<<<(E + 255) / 256, 256, 0, s2>>>(ei, E);
    k_scan<<<1, 1024, SCAN_SMEM, s2>>>();
    k_fill<<<(E + NN + 255) / 256, 256, 0, s2>>>(E);
    cudaEventRecord(e1, s2);

    // main: fp16 conversion + layer-1 GEMM (+fused att scores)
    k_f2h<<<((XH_N + W1_N + W2_N) / 4 + 255) / 256, 256>>>(x, W1, W2);
    gemm_fp16<1><<<dim3(512 / BN, (NN + BM - 1) / BM), 256, GEMM_SMEM>>>(
        p_xh, p_W1h, p_h1, NN, 256, 512, as1, ad1, p_as1, p_ad1);

    cudaStreamWaitEvent(0, e1, 0);   // join CSR before softmax

    k_softmax1<<<NN / 8, 256>>>();
    k_aggregate1<<<(NN * 4) / 8, 256>>>(b1);

    // layer 2
    cudaMemsetAsync(p_as2, 0, NN * sizeof(float), 0);
    cudaMemsetAsync(p_ad2, 0, NN * sizeof(float), 0);
    gemm_fp16<2><<<dim3(256 / BN, (NN + BM - 1) / BM), 256, GEMM_SMEM>>>(
        p_out1h, p_W2h, p_h2, NN, 512, 256, as2, ad2, p_as2, p_ad2);

    k_softmax2<<<NN / 8, 256>>>();
    k_aggregate2<<<NN / 8, 256>>>(b2, out);
}